// round 3
// baseline (speedup 1.0000x reference)
#include <cuda_runtime.h>
#include <math.h>

#define T_N  4096
#define EMB  384
#define HID  256
#define NH   4
#define HD   64
#define MD   32
#define S0   33
#define NS   4063

__device__ float g_h  [T_N * HID];
__device__ float g_x  [T_N * HID];
__device__ float g_Wh [T_N * HID];
__device__ float g_hn [T_N * HID];
__device__ float g_src[NH * T_N];
__device__ float g_dst[NH * T_N];
__device__ float g_dmax[NH];
__device__ float g_scal[4];
__device__ float g_scores[NS];
__device__ float g_cosf[NS];
__device__ float g_aw[NS];

__device__ __forceinline__ float warpSum(float v) {
    #pragma unroll
    for (int o = 16; o; o >>= 1) v += __shfl_xor_sync(0xffffffffu, v, o);
    return v;
}
__device__ __forceinline__ float warpMax(float v) {
    #pragma unroll
    for (int o = 16; o; o >>= 1) v = fmaxf(v, __shfl_xor_sync(0xffffffffu, v, o));
    return v;
}
__device__ float blockSum256(float v) {
    __shared__ float sh[8];
    int w = threadIdx.x >> 5, l = threadIdx.x & 31;
    v = warpSum(v);
    if (l == 0) sh[w] = v;
    __syncthreads();
    float s = (threadIdx.x < 8) ? sh[threadIdx.x] : 0.f;
    if (w == 0) { s = warpSum(s); if (l == 0) sh[0] = s; }
    __syncthreads();
    float r = sh[0];
    __syncthreads();
    return r;
}

// ---------------- generic 16-row GEMM ----------------
#define GEMM_STEP(WV, KK)                                                     \
    {                                                                         \
        const float4* av = (const float4*)&sa[(KK) * 16];                     \
        float4 a0 = av[0], a1 = av[1], a2 = av[2], a3 = av[3];                \
        acc[0]  += a0.x * (WV); acc[1]  += a0.y * (WV);                       \
        acc[2]  += a0.z * (WV); acc[3]  += a0.w * (WV);                       \
        acc[4]  += a1.x * (WV); acc[5]  += a1.y * (WV);                       \
        acc[6]  += a1.z * (WV); acc[7]  += a1.w * (WV);                       \
        acc[8]  += a2.x * (WV); acc[9]  += a2.y * (WV);                       \
        acc[10] += a2.z * (WV); acc[11] += a2.w * (WV);                       \
        acc[12] += a3.x * (WV); acc[13] += a3.y * (WV);                       \
        acc[14] += a3.z * (WV); acc[15] += a3.w * (WV);                       \
    }

__global__ void __launch_bounds__(256) gemm16(const float* __restrict__ A,
                                              const float* __restrict__ Wt,
                                              const float* __restrict__ bias,
                                              float* __restrict__ Cout,
                                              int K, int doRelu)
{
    __shared__ float sa[EMB * 16];
    int r0 = blockIdx.x * 16;
    for (int idx = threadIdx.x; idx < 16 * K; idx += 256) {
        int r = idx / K, k = idx - r * K;
        sa[k * 16 + r] = A[(size_t)(r0 + r) * K + k];
    }
    __syncthreads();
    float acc[16];
    #pragma unroll
    for (int r = 0; r < 16; r++) acc[r] = 0.f;
    int c = threadIdx.x;
    const float4* w4 = (const float4*)(Wt + (size_t)c * K);
    int K4 = K >> 2;
    for (int k4 = 0; k4 < K4; k4++) {
        float4 w = w4[k4];
        int kb = k4 * 4;
        GEMM_STEP(w.x, kb + 0)
        GEMM_STEP(w.y, kb + 1)
        GEMM_STEP(w.z, kb + 2)
        GEMM_STEP(w.w, kb + 3)
    }
    float b = bias ? bias[c] : 0.f;
    #pragma unroll
    for (int r = 0; r < 16; r++) {
        float v = acc[r] + b;
        if (doRelu) v = fmaxf(v, 0.f);
        Cout[(size_t)(r0 + r) * HID + c] = v;
    }
}

__global__ void __launch_bounds__(256) rownorm0(int slot)
{
    float v = g_h[threadIdx.x];
    float s = blockSum256(v * v);
    if (threadIdx.x == 0) g_scal[slot] = 1.f / (sqrtf(s) + 1e-8f);
}

__global__ void __launch_bounds__(256) cos_update()
{
    __shared__ float q[HID];
    int tid = threadIdx.x;
    q[tid] = g_h[tid];
    __syncthreads();
    int w = tid >> 5, l = tid & 31;
    int j = blockIdx.x * 8 + w;
    if (j >= NS) return;
    float* s = &g_h[(size_t)(S0 + j) * HID];
    float sv[8];
    float qs = 0.f, ss = 0.f;
    #pragma unroll
    for (int e = 0; e < 8; e++) {
        float x = s[l + 32 * e];
        sv[e] = x;
        qs += q[l + 32 * e] * x;
        ss += x * x;
    }
    qs = warpSum(qs);
    ss = warpSum(ss);
    float cs = qs * g_scal[0] / (sqrtf(ss) + 1e-8f);
    #pragma unroll
    for (int e = 0; e < 8; e++)
        s[l + 32 * e] = sv[e] + 0.8f * q[l + 32 * e] * cs;
}

__global__ void __launch_bounds__(256) ln_k(const float* __restrict__ scale,
                                            const float* __restrict__ bias)
{
    int row = blockIdx.x, tid = threadIdx.x;
    float v = g_h[(size_t)row * HID + tid];
    float mu = blockSum256(v) * (1.f / HID);
    float d = v - mu;
    float var = blockSum256(d * d) * (1.f / HID);
    g_x[(size_t)row * HID + tid] = d * rsqrtf(var + 1e-5f) * scale[tid] + bias[tid];
}

__global__ void __launch_bounds__(256) srcdst_k(const float* __restrict__ ga)
{
    int w = threadIdx.x >> 5, l = threadIdx.x & 31;
    int gid = blockIdx.x * 8 + w;
    int n = gid >> 2, hh = gid & 3;
    const float* wp = &g_Wh[(size_t)n * HID + hh * HD];
    float v0 = wp[l], v1 = wp[l + 32];
    const float* a = ga + hh * 2 * HD;
    float s = v0 * a[l] + v1 * a[l + 32];
    float d = v0 * a[HD + l] + v1 * a[HD + l + 32];
    s = warpSum(s);
    d = warpSum(d);
    if (l == 0) { g_src[hh * T_N + n] = s; g_dst[hh * T_N + n] = d; }
}

__global__ void __launch_bounds__(256) dmax_k()
{
    int h = blockIdx.x;
    float m = -1e30f;
    for (int i = threadIdx.x; i < T_N; i += 256) m = fmaxf(m, g_dst[h * T_N + i]);
    __shared__ float sh[8];
    int w = threadIdx.x >> 5, l = threadIdx.x & 31;
    m = warpMax(m);
    if (l == 0) sh[w] = m;
    __syncthreads();
    if (threadIdx.x == 0) {
        float mm = sh[0];
        #pragma unroll
        for (int i = 1; i < 8; i++) mm = fmaxf(mm, sh[i]);
        g_dmax[h] = mm;
    }
}

// ---------------- fused masked-softmax attention + P@Wh (v2) ----------------
// 32 rows/CTA, grid 128 (~1 CTA/SM, 1 wave). Double-buffered weight tile,
// one barrier per j-tile. Phase A: warp w -> head w&3, rows (w>>2)*16..+15,
// lane = j-local; adj/dst prefetched one tile ahead. Layout w_s[..][36] gives
// 4-way STS and 16B-aligned broadcast LDS.128 in phase B (4 rows per access).
// Phase B: warp w -> rows (w&1)*16..+15, head w>>1, cols col0 & col0+32,
// accumulated as packed fma.rn.f32x2.
__global__ void __launch_bounds__(256) attn_k(const int* __restrict__ adj)
{
    __shared__ __align__(16) float w_s[2][NH][32][36];
    __shared__ float2 srcms[32][NH];
    __shared__ float  zfin[32][NH];

    int tid = threadIdx.x, w = tid >> 5, lane = tid & 31;
    int row0 = blockIdx.x * 32;

    if (tid < 128) {
        int r = tid >> 2, hh = tid & 3;
        float s = g_src[hh * T_N + row0 + r];
        float m = s + g_dmax[hh];
        m = (m > 0.f) ? m : 0.2f * m;      // lrelu of upper bound >= all e_ij
        srcms[r][hh] = make_float2(s, m);
    }
    __syncthreads();

    int ah = w & 3, rbase = (w >> 2) * 16;
    const int*   adjp = adj + (size_t)(row0 + rbase) * T_N + lane;
    const float* dstp = g_dst + ah * T_N + lane;

    int rh = w & 1, cq = w >> 1;
    int col0 = cq * 64 + lane;

    float zacc[16];
    #pragma unroll
    for (int i = 0; i < 16; i++) zacc[i] = 0.f;
    unsigned long long acc2[8][2];
    #pragma unroll
    for (int i = 0; i < 8; i++) { acc2[i][0] = 0ull; acc2[i][1] = 0ull; }

    int av[16];
    float dv;
    #pragma unroll
    for (int i = 0; i < 16; i++) av[i] = adjp[(size_t)i * T_N];
    dv = dstp[0];

    for (int t = 0; t < T_N / 32; t++) {
        int j0 = t * 32, buf = t & 1;

        // phase A: masked exp weights into w_s[buf]
        #pragma unroll
        for (int i = 0; i < 16; i++) {
            float2 sm = srcms[rbase + i][ah];
            float ev = sm.x + dv;
            ev = (ev > 0.f) ? ev : 0.2f * ev;
            float wv = av[i] ? __expf(ev - sm.y) : 0.f;
            w_s[buf][ah][lane][rbase + i] = wv;
            zacc[i] += wv;
        }
        if (t < T_N / 32 - 1) {
            #pragma unroll
            for (int i = 0; i < 16; i++) av[i] = adjp[(size_t)i * T_N + j0 + 32];
            dv = dstp[j0 + 32];
        }
        __syncthreads();

        // phase B: acc += w * Wh
        const float* whp = g_Wh + (size_t)j0 * HID + col0;
        #pragma unroll 8
        for (int jl = 0; jl < 32; jl++) {
            float b0 = whp[jl * HID], b1 = whp[jl * HID + 32];
            unsigned long long w0d, w1d;
            asm("mov.b64 %0, {%1,%1};" : "=l"(w0d) : "r"(__float_as_uint(b0)));
            asm("mov.b64 %0, {%1,%1};" : "=l"(w1d) : "r"(__float_as_uint(b1)));
            const ulonglong2* wp = (const ulonglong2*)&w_s[buf][cq][jl][rh * 16];
            #pragma unroll
            for (int g = 0; g < 4; g++) {
                ulonglong2 wv = wp[g];
                asm("fma.rn.f32x2 %0, %1, %2, %0;" : "+l"(acc2[2*g  ][0]) : "l"(wv.x), "l"(w0d));
                asm("fma.rn.f32x2 %0, %1, %2, %0;" : "+l"(acc2[2*g  ][1]) : "l"(wv.x), "l"(w1d));
                asm("fma.rn.f32x2 %0, %1, %2, %0;" : "+l"(acc2[2*g+1][0]) : "l"(wv.y), "l"(w0d));
                asm("fma.rn.f32x2 %0, %1, %2, %0;" : "+l"(acc2[2*g+1][1]) : "l"(wv.y), "l"(w1d));
            }
        }
        // no second barrier: next phase A writes the other buffer
    }

    // Z reduce: each (row, head) owned by exactly one phase-A warp
    #pragma unroll
    for (int i = 0; i < 16; i++) {
        float z = warpSum(zacc[i]);
        if (lane == i) zfin[rbase + i][ah] = 1.f / z;
    }
    __syncthreads();

    #pragma unroll
    for (int g = 0; g < 4; g++) {
        #pragma unroll
        for (int e = 0; e < 2; e++) {
            int r = rh * 16 + 4 * g + 2 * e;
            float zi0 = zfin[r][cq], zi1 = zfin[r + 1][cq];
            #pragma unroll
            for (int c = 0; c < 2; c++) {
                unsigned long long a = acc2[2 * g + e][c];
                float lo = __uint_as_float((unsigned)(a & 0xffffffffull));
                float hi = __uint_as_float((unsigned)(a >> 32));
                g_hn[(size_t)(row0 + r)     * HID + col0 + 32 * c] = lo * zi0;
                g_hn[(size_t)(row0 + r + 1) * HID + col0 + 32 * c] = hi * zi1;
            }
        }
    }
}

__global__ void __launch_bounds__(256) combine_k()
{
    size_t i = (size_t)blockIdx.x * 256 + threadIdx.x;
    float hv = g_h[i], nv = g_hn[i];
    g_h[i] = 0.5f * fmaxf(nv, 0.f) + 0.5f * hv;
}

__global__ void __launch_bounds__(256) scorecos_k()
{
    __shared__ float q[HID];
    int tid = threadIdx.x;
    q[tid] = g_h[tid];
    __syncthreads();
    int w = tid >> 5, l = tid & 31;
    int j = blockIdx.x * 8 + w;
    if (j >= NS) return;
    const float* s = &g_h[(size_t)(S0 + j) * HID];
    float qs = 0.f, ss = 0.f;
    #pragma unroll
    for (int e = 0; e < 8; e++) {
        float x = s[l + 32 * e];
        qs += q[l + 32 * e] * x;
        ss += x * x;
    }
    qs = warpSum(qs);
    ss = warpSum(ss);
    if (l == 0) {
        g_scores[j] = qs * (1.0f / 16.0f);
        g_cosf[j] = qs * g_scal[1] / (sqrtf(ss) + 1e-8f);
    }
}

__global__ void __launch_bounds__(1024) softmax_k()
{
    __shared__ float sh[32];
    int tid = threadIdx.x, w = tid >> 5, l = tid & 31;

    float m = -1e30f;
    for (int i = tid; i < NS; i += 1024) m = fmaxf(m, g_scores[i]);
    m = warpMax(m);
    if (l == 0) sh[w] = m;
    __syncthreads();
    if (w == 0) { float mm = sh[l]; mm = warpMax(mm); if (l == 0) sh[0] = mm; }
    __syncthreads();
    m = sh[0];
    __syncthreads();

    float sum = 0.f;
    for (int i = tid; i < NS; i += 1024) {
        float e = __expf(g_scores[i] - m);
        g_aw[i] = e;
        sum += e;
    }
    sum = warpSum(sum);
    if (l == 0) sh[w] = sum;
    __syncthreads();
    if (w == 0) { float ss = sh[l]; ss = warpSum(ss); if (l == 0) sh[0] = ss; }
    __syncthreads();
    float inv = 1.f / sh[0];
    for (int i = tid; i < NS; i += 1024) g_aw[i] *= inv;
}

// ---------------- fusion MLP + output head (v2: coalesced fw staging) ----------------
__global__ void __launch_bounds__(256) fusion_k(const float* __restrict__ fw,
                                                const float* __restrict__ fb,
                                                const float* __restrict__ ow,
                                                const float* __restrict__ obp,
                                                float* __restrict__ out)
{
    __shared__ float fws[256][33];
    __shared__ __align__(16) float feat_s[32][20];
    __shared__ float awv[16], cosv[16];
    __shared__ float red2[16][8];
    int tid = threadIdx.x;
    int w = tid >> 5, lane = tid & 31;
    int j0 = blockIdx.x * 16;

    if (tid < 16) {
        int j = j0 + tid;
        awv[tid]  = (j < NS) ? g_aw[j]   : 0.f;
        cosv[tid] = (j < NS) ? g_cosf[j] : 0.f;
    }
    __syncthreads();

    unsigned long long acc2[8];
    #pragma unroll
    for (int i = 0; i < 8; i++) acc2[i] = 0ull;
    int c = tid;

    for (int k0 = 0; k0 < 512; k0 += 32) {
        #pragma unroll 8
        for (int rr = 0; rr < 32; rr++)
            fws[w * 32 + rr][lane] = fw[(size_t)(w * 32 + rr) * 514 + k0 + lane];
        #pragma unroll
        for (int q = 0; q < 2; q++) {
            int idx = tid + q * 256;
            int r = idx >> 5, kk = idx & 31;
            int k = k0 + kk;
            int j = j0 + r;
            float v = 0.f;
            if (j < NS) {
                if (k < 256) v = g_h[(size_t)(S0 + j) * HID + k];
                else         v = g_h[k - 256] * (awv[r] + 0.5f);
            }
            feat_s[kk][r] = v;
        }
        __syncthreads();

        #pragma unroll 8
        for (int kk = 0; kk < 32; kk++) {
            float wv = fws[c][kk];
            unsigned long long wvd;
            asm("mov.b64 %0, {%1,%1};" : "=l"(wvd) : "r"(__float_as_uint(wv)));
            const ulonglong2* fp = (const ulonglong2*)&feat_s[kk][0];
            #pragma unroll
            for (int q = 0; q < 4; q++) {
                ulonglong2 fv = fp[q];
                asm("fma.rn.f32x2 %0, %1, %2, %0;" : "+l"(acc2[2*q  ]) : "l"(fv.x), "l"(wvd));
                asm("fma.rn.f32x2 %0, %1, %2, %0;" : "+l"(acc2[2*q+1]) : "l"(fv.y), "l"(wvd));
            }
        }
        __syncthreads();
    }

    float acc[16];
    #pragma unroll
    for (int q = 0; q < 8; q++) {
        acc[2*q]   = __uint_as_float((unsigned)(acc2[q] & 0xffffffffull));
        acc[2*q+1] = __uint_as_float((unsigned)(acc2[q] >> 32));
    }
    float w512 = fw[(size_t)c * 514 + 512];
    float w513 = fw[(size_t)c * 514 + 513];
    #pragma unroll
    for (int r = 0; r < 16; r++) acc[r] += w512 * cosv[r] + w513 * awv[r];

    float fbv = fb[c];
    float owv = ow[c];
    #pragma unroll
    for (int r = 0; r < 16; r++) {
        float gv = fmaxf(acc[r] + fbv, 0.f) * owv;
        gv = warpSum(gv);
        if (lane == 0) red2[r][w] = gv;
    }
    __syncthreads();
    if (tid < 16) {
        float s = 0.f;
        #pragma unroll
        for (int ww = 0; ww < 8; ww++) s += red2[tid][ww];
        int j = j0 + tid;
        if (j < NS) out[j] = s + obp[0] + 0.5f * cosv[tid];
    }
}

// ---------------- launch ----------------
extern "C" void kernel_launch(void* const* d_in, const int* in_sizes, int n_in,
                              void* d_out, int out_size)
{
    const float* emb    = (const float*)d_in[0];
    const int*   adj    = (const int*)  d_in[1];
    const float* proj_w = (const float*)d_in[3];
    const float* proj_b = (const float*)d_in[4];
    const float* ln_s   = (const float*)d_in[5];
    const float* ln_b   = (const float*)d_in[6];
    const float* gat_W  = (const float*)d_in[7];
    const float* gat_a  = (const float*)d_in[8];
    const float* fw     = (const float*)d_in[9];
    const float* fb     = (const float*)d_in[10];
    const float* ow     = (const float*)d_in[11];
    const float* ob     = (const float*)d_in[12];
    float* out = (float*)d_out;

    float *hP, *xP, *whP;
    cudaGetSymbolAddress((void**)&hP,  g_h);
    cudaGetSymbolAddress((void**)&xP,  g_x);
    cudaGetSymbolAddress((void**)&whP, g_Wh);

    gemm16<<<T_N / 16, 256>>>(emb, proj_w, proj_b, hP, EMB, 1);
    rownorm0<<<1, 256>>>(0);
    cos_update<<<(NS + 7) / 8, 256>>>();

    for (int L = 0; L < 2; L++) {
        ln_k<<<T_N, 256>>>(ln_s + L * HID, ln_b + L * HID);
        gemm16<<<T_N / 16, 256>>>(xP, gat_W + (size_t)L * HID * HID, nullptr, whP, HID, 0);
        srcdst_k<<<T_N * NH / 8, 256>>>(gat_a + L * NH * 2 * HD);
        dmax_k<<<NH, 256>>>();
        attn_k<<<T_N / 32, 256>>>(adj);
        combine_k<<<T_N * HID / 256, 256>>>();
    }

    rownorm0<<<1, 256>>>(1);
    scorecos_k<<<(NS + 7) / 8, 256>>>();
    softmax_k<<<1, 1024>>>();
    fusion_k<<<(NS + 15) / 16, 256>>>(fw, fb, ow, ob, out);
}

// round 5
// speedup vs baseline: 2.7188x; 2.7188x over previous
#include <cuda_runtime.h>
#include <math.h>
#include <cstdint>

#define T_N  4096
#define EMB  384
#define HID  256
#define NH   4
#define HD   64
#define MD   32
#define S0   33
#define NS   4063

// tcgen05 only legal in family-specific (sm_103a) compilation passes.
#if defined(__CUDA_ARCH_FEAT_SM103_ALL) || defined(__CUDA_ARCH_FEAT_SM100_ALL) || defined(__CUDA_ARCH_FEAT_SM101_ALL)
#define HAS_TC 1
#else
#define HAS_TC 0
#endif

__device__ float g_h  [T_N * HID];
__device__ float g_x  [T_N * HID];
__device__ float g_Wh [T_N * HID];
__device__ float g_hn [T_N * HID];
__device__ float g_src[NH * T_N];
__device__ float g_dst[NH * T_N];
__device__ float g_dmax[NH];
__device__ float g_scal[4];
__device__ float g_scores[NS];
__device__ float g_cosf[NS];
__device__ float g_aw[NS];

__device__ __forceinline__ float warpSum(float v) {
    #pragma unroll
    for (int o = 16; o; o >>= 1) v += __shfl_xor_sync(0xffffffffu, v, o);
    return v;
}
__device__ __forceinline__ float warpMax(float v) {
    #pragma unroll
    for (int o = 16; o; o >>= 1) v = fmaxf(v, __shfl_xor_sync(0xffffffffu, v, o));
    return v;
}
__device__ float blockSum256(float v) {
    __shared__ float sh[8];
    int w = threadIdx.x >> 5, l = threadIdx.x & 31;
    v = warpSum(v);
    if (l == 0) sh[w] = v;
    __syncthreads();
    float s = (threadIdx.x < 8) ? sh[threadIdx.x] : 0.f;
    if (w == 0) { s = warpSum(s); if (l == 0) sh[0] = s; }
    __syncthreads();
    float r = sh[0];
    __syncthreads();
    return r;
}

// ======================= tcgen05 helpers (only referenced under HAS_TC) =======================
__device__ __forceinline__ uint32_t s2u(const void* p) {
    uint32_t a;
    asm("{ .reg .u64 t; cvta.to.shared.u64 t, %1; cvt.u32.u64 %0, t; }"
        : "=r"(a) : "l"(p));
    return a;
}
#if HAS_TC
__device__ __forceinline__ uint32_t elect_one() {
    uint32_t pred;
    asm volatile("{\n\t.reg .pred p;\n\telect.sync _|p, 0xFFFFFFFF;\n\t"
                 "selp.b32 %0, 1, 0, p;\n\t}" : "=r"(pred));
    return pred;
}
__device__ __forceinline__ void mbar_init(uint32_t addr, uint32_t cnt) {
    asm volatile("mbarrier.init.shared.b64 [%0], %1;" :: "r"(addr), "r"(cnt) : "memory");
}
__device__ __forceinline__ void mbar_wait(uint32_t addr, uint32_t parity) {
    asm volatile(
        "{\n\t.reg .pred P;\n\t"
        "WL%=:\n\t"
        "mbarrier.try_wait.parity.acquire.cta.shared::cta.b64 P, [%0], %1, 0x989680;\n\t"
        "@P bra WD%=;\n\t"
        "bra WL%=;\n\t"
        "WD%=:\n\t}"
        :: "r"(addr), "r"(parity) : "memory");
}
__device__ __forceinline__ void sts_tf32(uint32_t addr, float v) {
    uint32_t t;
    asm("cvt.rn.tf32.f32 %0, %1;" : "=r"(t) : "f"(v));
    asm volatile("st.shared.b32 [%0], %1;" :: "r"(addr), "r"(t) : "memory");
}
__device__ __forceinline__ void mma_tf32_ss(uint32_t d_tmem, uint64_t a_desc,
                                            uint64_t b_desc, uint32_t idesc,
                                            uint32_t en) {
    asm volatile(
        "{\n\t.reg .pred p;\n\tsetp.ne.u32 p, %4, 0;\n\t"
        "tcgen05.mma.cta_group::1.kind::tf32 [%0], %1, %2, %3, {%5, %5, %5, %5}, p;\n\t}"
        :: "r"(d_tmem), "l"(a_desc), "l"(b_desc), "r"(idesc), "r"(en), "r"(0u)
        : "memory");
}
__device__ __forceinline__ void tc_commit(uint32_t mbar) {
    asm volatile(
        "tcgen05.commit.cta_group::1.mbarrier::arrive::one.shared::cluster.b64 [%0];"
        :: "r"(mbar) : "memory");
}
#define TC_LD_X32(r, tmem_addr) \
    asm volatile( \
        "tcgen05.ld.sync.aligned.32x32b.x32.b32 " \
        "{%0, %1, %2, %3, %4, %5, %6, %7, " \
        " %8, %9, %10, %11, %12, %13, %14, %15, " \
        " %16, %17, %18, %19, %20, %21, %22, %23, " \
        " %24, %25, %26, %27, %28, %29, %30, %31}, [%32];" \
        : "=r"((r)[0]),  "=r"((r)[1]),  "=r"((r)[2]),  "=r"((r)[3]), \
          "=r"((r)[4]),  "=r"((r)[5]),  "=r"((r)[6]),  "=r"((r)[7]), \
          "=r"((r)[8]),  "=r"((r)[9]),  "=r"((r)[10]), "=r"((r)[11]), \
          "=r"((r)[12]), "=r"((r)[13]), "=r"((r)[14]), "=r"((r)[15]), \
          "=r"((r)[16]), "=r"((r)[17]), "=r"((r)[18]), "=r"((r)[19]), \
          "=r"((r)[20]), "=r"((r)[21]), "=r"((r)[22]), "=r"((r)[23]), \
          "=r"((r)[24]), "=r"((r)[25]), "=r"((r)[26]), "=r"((r)[27]), \
          "=r"((r)[28]), "=r"((r)[29]), "=r"((r)[30]), "=r"((r)[31]) \
        : "r"(tmem_addr))
#endif // HAS_TC

__device__ __forceinline__ uint32_t sw128(uint32_t off) {
    return off ^ ((off >> 3) & 0x70);
}
__device__ __forceinline__ float ex2f(float x) {
    float r;
    asm("ex2.approx.f32 %0, %1;" : "=f"(r) : "f"(x));
    return r;
}

// smem desc: SW128, version=1(Blackwell), SBO=64, LBO=1
#define DESC_BASE ((2ull << 61) | (1ull << 46) | (64ull << 32) | (1ull << 16))
// idesc: dtype=F32(1<<4), atype=TF32(2<<7), btype=TF32(2<<10), N=64(8<<17), M=128(8<<24)
#define TF32_IDESC ((1u << 4) | (2u << 7) | (2u << 10) | (8u << 17) | (8u << 24))

#define SM_P0    0
#define SM_P1    16384
#define SM_B0    32768
#define SM_B1    40960
#define SM_TPTR  49152
#define SM_MB0   49168
#define SM_MB1   49176
#define SM_ZF    49184
#define SM_TOTAL (49184 + 512 + 1024)

// ======================= generic 16-row GEMM =======================
#define GEMM_STEP(WV, KK)                                                     \
    {                                                                         \
        const float4* av = (const float4*)&sa[(KK) * 16];                     \
        float4 a0 = av[0], a1 = av[1], a2 = av[2], a3 = av[3];                \
        acc[0]  += a0.x * (WV); acc[1]  += a0.y * (WV);                       \
        acc[2]  += a0.z * (WV); acc[3]  += a0.w * (WV);                       \
        acc[4]  += a1.x * (WV); acc[5]  += a1.y * (WV);                       \
        acc[6]  += a1.z * (WV); acc[7]  += a1.w * (WV);                       \
        acc[8]  += a2.x * (WV); acc[9]  += a2.y * (WV);                       \
        acc[10] += a2.z * (WV); acc[11] += a2.w * (WV);                       \
        acc[12] += a3.x * (WV); acc[13] += a3.y * (WV);                       \
        acc[14] += a3.z * (WV); acc[15] += a3.w * (WV);                       \
    }

__global__ void __launch_bounds__(256) gemm16(const float* __restrict__ A,
                                              const float* __restrict__ Wt,
                                              const float* __restrict__ bias,
                                              float* __restrict__ Cout,
                                              int K, int doRelu)
{
    __shared__ float sa[EMB * 16];
    int r0 = blockIdx.x * 16;
    for (int idx = threadIdx.x; idx < 16 * K; idx += 256) {
        int r = idx / K, k = idx - r * K;
        sa[k * 16 + r] = A[(size_t)(r0 + r) * K + k];
    }
    __syncthreads();
    float acc[16];
    #pragma unroll
    for (int r = 0; r < 16; r++) acc[r] = 0.f;
    int c = threadIdx.x;
    const float4* w4 = (const float4*)(Wt + (size_t)c * K);
    int K4 = K >> 2;
    for (int k4 = 0; k4 < K4; k4++) {
        float4 w = w4[k4];
        int kb = k4 * 4;
        GEMM_STEP(w.x, kb + 0)
        GEMM_STEP(w.y, kb + 1)
        GEMM_STEP(w.z, kb + 2)
        GEMM_STEP(w.w, kb + 3)
    }
    float b = bias ? bias[c] : 0.f;
    #pragma unroll
    for (int r = 0; r < 16; r++) {
        float v = acc[r] + b;
        if (doRelu) v = fmaxf(v, 0.f);
        Cout[(size_t)(r0 + r) * HID + c] = v;
    }
}

__global__ void __launch_bounds__(256) rownorm0(int slot)
{
    float v = g_h[threadIdx.x];
    float s = blockSum256(v * v);
    if (threadIdx.x == 0) g_scal[slot] = 1.f / (sqrtf(s) + 1e-8f);
}

__global__ void __launch_bounds__(256) cos_update()
{
    __shared__ float q[HID];
    int tid = threadIdx.x;
    q[tid] = g_h[tid];
    __syncthreads();
    int w = tid >> 5, l = tid & 31;
    int j = blockIdx.x * 8 + w;
    if (j >= NS) return;
    float* s = &g_h[(size_t)(S0 + j) * HID];
    float sv[8];
    float qs = 0.f, ss = 0.f;
    #pragma unroll
    for (int e = 0; e < 8; e++) {
        float x = s[l + 32 * e];
        sv[e] = x;
        qs += q[l + 32 * e] * x;
        ss += x * x;
    }
    qs = warpSum(qs);
    ss = warpSum(ss);
    float cs = qs * g_scal[0] / (sqrtf(ss) + 1e-8f);
    #pragma unroll
    for (int e = 0; e < 8; e++)
        s[l + 32 * e] = sv[e] + 0.8f * q[l + 32 * e] * cs;
}

__global__ void __launch_bounds__(256) ln_k(const float* __restrict__ scale,
                                            const float* __restrict__ bias)
{
    int row = blockIdx.x, tid = threadIdx.x;
    float v = g_h[(size_t)row * HID + tid];
    float mu = blockSum256(v) * (1.f / HID);
    float d = v - mu;
    float var = blockSum256(d * d) * (1.f / HID);
    g_x[(size_t)row * HID + tid] = d * rsqrtf(var + 1e-5f) * scale[tid] + bias[tid];
}

__global__ void __launch_bounds__(256) srcdst_k(const float* __restrict__ ga)
{
    int w = threadIdx.x >> 5, l = threadIdx.x & 31;
    int gid = blockIdx.x * 8 + w;
    int n = gid >> 2, hh = gid & 3;
    const float* wp = &g_Wh[(size_t)n * HID + hh * HD];
    float v0 = wp[l], v1 = wp[l + 32];
    const float* a = ga + hh * 2 * HD;
    float s = v0 * a[l] + v1 * a[l + 32];
    float d = v0 * a[HD + l] + v1 * a[HD + l + 32];
    s = warpSum(s);
    d = warpSum(d);
    if (l == 0) { g_src[hh * T_N + n] = s; g_dst[hh * T_N + n] = d; }
}

__global__ void __launch_bounds__(256) dmax_k()
{
    int h = blockIdx.x;
    float m = -1e30f;
    for (int i = threadIdx.x; i < T_N; i += 256) m = fmaxf(m, g_dst[h * T_N + i]);
    __shared__ float sh[8];
    int w = threadIdx.x >> 5, l = threadIdx.x & 31;
    m = warpMax(m);
    if (l == 0) sh[w] = m;
    __syncthreads();
    if (threadIdx.x == 0) {
        float mm = sh[0];
        #pragma unroll
        for (int i = 1; i < 8; i++) mm = fmaxf(mm, sh[i]);
        g_dmax[h] = mm;
    }
}

// ============== attention: one CTA = (128 rows, 1 head) ==============
// sm_103a pass: tcgen05 tf32 SS MMA, double-buffered (P,B) tiles, MMA hidden
// behind generation. Non-'a' pass: correct SIMT fallback (never runs when the
// sm_103a cubin is present).
__global__ void __launch_bounds__(256) attn_tc(const int* __restrict__ adj)
{
    extern __shared__ char dsm[];
    uint32_t raw = s2u(dsm);
    uint32_t base = (raw + 1023u) & ~1023u;
    char* smc = dsm + (base - raw);
    float* zfin = (float*)(smc + SM_ZF);

    int tid = threadIdx.x, w = tid >> 5, lane = tid & 31;
    int h = blockIdx.x & 3;
    int i0 = (blockIdx.x >> 2) * 128;

    const float L2E = 1.44269504f;
    float srcv[16], mlog[16], zacc[16];
    float dmax = g_dmax[h];
    #pragma unroll
    for (int i = 0; i < 16; i++) {
        float s = g_src[h * T_N + i0 + w * 16 + i];
        float m = s + dmax;
        m = fmaxf(m, 0.2f * m);
        srcv[i] = s;
        mlog[i] = m * L2E;
        zacc[i] = 0.f;
    }

    const int* adjp = adj + (size_t)(i0 + w * 16) * T_N + lane;
    const float* dstp = g_dst + h * T_N + lane;
    const float* whp0 = g_Wh + h * 64;
    const int NT = T_N / 32;

    int av[16];
    float dval;
    #pragma unroll
    for (int i = 0; i < 16; i++) av[i] = adjp[(size_t)i * T_N];
    dval = dstp[0];

#if HAS_TC
    if (w == 0)
        asm volatile("tcgen05.alloc.cta_group::1.sync.aligned.shared::cta.b32 [%0], %1;"
                     :: "r"(base + SM_TPTR), "r"(64u) : "memory");
    if (tid == 0) { mbar_init(base + SM_MB0, 1); mbar_init(base + SM_MB1, 1); }
    __syncthreads();
    uint32_t tmem;
    asm volatile("ld.shared.b32 %0, [%1];" : "=r"(tmem) : "r"(base + SM_TPTR));

    int wp0 = 0, wp1 = 0;

    for (int t = 0; t < NT; t++) {
        int buf = t & 1;
        int j0 = t * 32;
        uint32_t Pb = base + (buf ? SM_P1 : SM_P0);
        uint32_t Bb = base + (buf ? SM_B1 : SM_B0);
        uint32_t mb = base + (buf ? SM_MB1 : SM_MB0);

        if (t >= 2) {
            if (buf == 0) { mbar_wait(base + SM_MB0, wp0); wp0 ^= 1; }
            else          { mbar_wait(base + SM_MB1, wp1); wp1 ^= 1; }
        }

        // B tile: Bs[n][k] = Wh[j0+k][h*64+n]  (64 x 32 tf32, SW128)
        #pragma unroll
        for (int q = 0; q < 8; q++) {
            int idx = tid + q * 256;
            int n = idx & 63, k = idx >> 6;
            float v = whp0[(size_t)(j0 + k) * HID + n];
            sts_tf32(Bb + sw128((uint32_t)(n * 128 + k * 4)), v);
        }

        // P tile: rows w*16..+15, j = j0+lane
        #pragma unroll
        for (int i = 0; i < 16; i++) {
            float ev = srcv[i] + dval;
            ev = fmaxf(ev, 0.2f * ev);
            float wv = ex2f(fmaf(ev, L2E, -mlog[i]));
            wv = av[i] ? wv : 0.f;
            zacc[i] += wv;
            sts_tf32(Pb + sw128((uint32_t)((w * 16 + i) * 128 + lane * 4)), wv);
        }

        if (t < NT - 1) {
            #pragma unroll
            for (int i = 0; i < 16; i++) av[i] = adjp[(size_t)i * T_N + j0 + 32];
            dval = dstp[j0 + 32];
        }

        asm volatile("fence.proxy.async.shared::cta;" ::: "memory");
        __syncthreads();

        if (w == 0 && elect_one()) {
            uint64_t ad = DESC_BASE | ((uint64_t)(Pb >> 4) & 0x3FFF);
            uint64_t bd = DESC_BASE | ((uint64_t)(Bb >> 4) & 0x3FFF);
            #pragma unroll
            for (int c = 0; c < 4; c++)
                mma_tf32_ss(tmem, ad + c * 2, bd + c * 2, TF32_IDESC,
                            (t > 0 || c > 0) ? 1u : 0u);
            tc_commit(mb);
        }
    }

    #pragma unroll
    for (int i = 0; i < 16; i++) {
        float z = warpSum(zacc[i]);
        if (lane == i) zfin[w * 16 + i] = 1.f / z;
    }
    __syncthreads();

    mbar_wait(base + SM_MB1, wp1);
    asm volatile("tcgen05.fence::after_thread_sync;" ::: "memory");

    if (w < 4) {
        uint32_t dr[64];
        TC_LD_X32(dr, tmem);
        TC_LD_X32(dr + 32, tmem + 32);
        asm volatile("tcgen05.wait::ld.sync.aligned;" ::: "memory");
        int row = w * 32 + lane;
        float zi = zfin[row];
        float4* op = (float4*)&g_hn[(size_t)(i0 + row) * HID + h * 64];
        #pragma unroll
        for (int q = 0; q < 16; q++) {
            op[q] = make_float4(__uint_as_float(dr[4 * q])     * zi,
                                __uint_as_float(dr[4 * q + 1]) * zi,
                                __uint_as_float(dr[4 * q + 2]) * zi,
                                __uint_as_float(dr[4 * q + 3]) * zi);
        }
    }
    __syncthreads();
    if (w == 0) {
        asm volatile("tcgen05.relinquish_alloc_permit.cta_group::1.sync.aligned;");
        asm volatile("tcgen05.dealloc.cta_group::1.sync.aligned.b32 %0, %1;"
                     :: "r"(tmem), "r"(64u));
    }
#else
    // -------- SIMT fallback (compiled only for non-sm_103a passes) --------
    float* P = (float*)(smc + SM_P0);           // [128][33]
    int col = tid & 63, rhalf = tid >> 6;
    float acc[32];
    #pragma unroll
    for (int r = 0; r < 32; r++) acc[r] = 0.f;
    __syncthreads();

    for (int t = 0; t < NT; t++) {
        int j0 = t * 32;
        #pragma unroll
        for (int i = 0; i < 16; i++) {
            float ev = srcv[i] + dval;
            ev = fmaxf(ev, 0.2f * ev);
            float wv = ex2f(fmaf(ev, L2E, -mlog[i]));
            wv = av[i] ? wv : 0.f;
            zacc[i] += wv;
            P[(w * 16 + i) * 33 + lane] = wv;
        }
        if (t < NT - 1) {
            #pragma unroll
            for (int i = 0; i < 16; i++) av[i] = adjp[(size_t)i * T_N + j0 + 32];
            dval = dstp[j0 + 32];
        }
        __syncthreads();

        const float* whc = whp0 + (size_t)j0 * HID + col;
        #pragma unroll 4
        for (int jl = 0; jl < 32; jl++) {
            float b = whc[(size_t)jl * HID];
            const float* Pc = P + (rhalf * 32) * 33 + jl;
            #pragma unroll
            for (int r = 0; r < 32; r++) acc[r] += Pc[r * 33] * b;
        }
        __syncthreads();
    }

    #pragma unroll
    for (int i = 0; i < 16; i++) {
        float z = warpSum(zacc[i]);
        if (lane == i) zfin[w * 16 + i] = 1.f / z;
    }
    __syncthreads();
    #pragma unroll
    for (int r = 0; r < 32; r++) {
        int row = rhalf * 32 + r;
        g_hn[(size_t)(i0 + row) * HID + h * 64 + col] = acc[r] * zfin[row];
    }
#endif
}

__global__ void __launch_bounds__(256) combine_k()
{
    size_t i = (size_t)blockIdx.x * 256 + threadIdx.x;
    float hv = g_h[i], nv = g_hn[i];
    g_h[i] = 0.5f * fmaxf(nv, 0.f) + 0.5f * hv;
}

__global__ void __launch_bounds__(256) scorecos_k()
{
    __shared__ float q[HID];
    int tid = threadIdx.x;
    q[tid] = g_h[tid];
    __syncthreads();
    int w = tid >> 5, l = tid & 31;
    int j = blockIdx.x * 8 + w;
    if (j >= NS) return;
    const float* s = &g_h[(size_t)(S0 + j) * HID];
    float qs = 0.f, ss = 0.f;
    #pragma unroll
    for (int e = 0; e < 8; e++) {
        float x = s[l + 32 * e];
        qs += q[l + 32 * e] * x;
        ss += x * x;
    }
    qs = warpSum(qs);
    ss = warpSum(ss);
    if (l == 0) {
        g_scores[j] = qs * (1.0f / 16.0f);
        g_cosf[j] = qs * g_scal[1] / (sqrtf(ss) + 1e-8f);
    }
}

__global__ void __launch_bounds__(1024) softmax_k()
{
    __shared__ float sh[32];
    int tid = threadIdx.x, w = tid >> 5, l = tid & 31;

    float m = -1e30f;
    for (int i = tid; i < NS; i += 1024) m = fmaxf(m, g_scores[i]);
    m = warpMax(m);
    if (l == 0) sh[w] = m;
    __syncthreads();
    if (w == 0) { float mm = sh[l]; mm = warpMax(mm); if (l == 0) sh[0] = mm; }
    __syncthreads();
    m = sh[0];
    __syncthreads();

    float sum = 0.f;
    for (int i = tid; i < NS; i += 1024) {
        float e = __expf(g_scores[i] - m);
        g_aw[i] = e;
        sum += e;
    }
    sum = warpSum(sum);
    if (l == 0) sh[w] = sum;
    __syncthreads();
    if (w == 0) { float ss = sh[l]; ss = warpSum(ss); if (l == 0) sh[0] = ss; }
    __syncthreads();
    float inv = 1.f / sh[0];
    for (int i = tid; i < NS; i += 1024) g_aw[i] *= inv;
}

__global__ void __launch_bounds__(256) fusion_k(const float* __restrict__ fw,
                                                const float* __restrict__ fb,
                                                const float* __restrict__ ow,
                                                const float* __restrict__ obp,
                                                float* __restrict__ out)
{
    __shared__ float fws[256][33];
    __shared__ __align__(16) float feat_s[32][20];
    __shared__ float awv[16], cosv[16];
    __shared__ float red2[16][8];
    int tid = threadIdx.x;
    int w = tid >> 5, lane = tid & 31;
    int j0 = blockIdx.x * 16;

    if (tid < 16) {
        int j = j0 + tid;
        awv[tid]  = (j < NS) ? g_aw[j]   : 0.f;
        cosv[tid] = (j < NS) ? g_cosf[j] : 0.f;
    }
    __syncthreads();

    unsigned long long acc2[8];
    #pragma unroll
    for (int i = 0; i < 8; i++) acc2[i] = 0ull;
    int c = tid;

    for (int k0 = 0; k0 < 512; k0 += 32) {
        #pragma unroll 8
        for (int rr = 0; rr < 32; rr++)
            fws[w * 32 + rr][lane] = fw[(size_t)(w * 32 + rr) * 514 + k0 + lane];
        #pragma unroll
        for (int q = 0; q < 2; q++) {
            int idx = tid + q * 256;
            int r = idx >> 5, kk = idx & 31;
            int k = k0 + kk;
            int j = j0 + r;
            float v = 0.f;
            if (j < NS) {
                if (k < 256) v = g_h[(size_t)(S0 + j) * HID + k];
                else         v = g_h[k - 256] * (awv[r] + 0.5f);
            }
            feat_s[kk][r] = v;
        }
        __syncthreads();

        #pragma unroll 8
        for (int kk = 0; kk < 32; kk++) {
            float wv = fws[c][kk];
            unsigned long long wvd;
            asm("mov.b64 %0, {%1,%1};" : "=l"(wvd) : "r"(__float_as_uint(wv)));
            const ulonglong2* fp = (const ulonglong2*)&feat_s[kk][0];
            #pragma unroll
            for (int q = 0; q < 4; q++) {
                ulonglong2 fv = fp[q];
                asm("fma.rn.f32x2 %0, %1, %2, %0;" : "+l"(acc2[2*q  ]) : "l"(fv.x), "l"(wvd));
                asm("fma.rn.f32x2 %0, %1, %2, %0;" : "+l"(acc2[2*q+1]) : "l"(fv.y), "l"(wvd));
            }
        }
        __syncthreads();
    }

    float acc[16];
    #pragma unroll
    for (int q = 0; q < 8; q++) {
        acc[2*q]   = __uint_as_float((unsigned)(acc2[q] & 0xffffffffull));
        acc[2*q+1] = __uint_as_float((unsigned)(acc2[q] >> 32));
    }
    float w512 = fw[(size_t)c * 514 + 512];
    float w513 = fw[(size_t)c * 514 + 513];
    #pragma unroll
    for (int r = 0; r < 16; r++) acc[r] += w512 * cosv[r] + w513 * awv[r];

    float fbv = fb[c];
    float owv = ow[c];
    #pragma unroll
    for (int r = 0; r < 16; r++) {
        float gv = fmaxf(acc[r] + fbv, 0.f) * owv;
        gv = warpSum(gv);
        if (lane == 0) red2[r][w] = gv;
    }
    __syncthreads();
    if (tid < 16) {
        float s = 0.f;
        #pragma unroll
        for (int ww = 0; ww < 8; ww++) s += red2[tid][ww];
        int j = j0 + tid;
        if (j < NS) out[j] = s + obp[0] + 0.5f * cosv[tid];
    }
}

// ---------------- launch ----------------
extern "C" void kernel_launch(void* const* d_in, const int* in_sizes, int n_in,
                              void* d_out, int out_size)
{
    const float* emb    = (const float*)d_in[0];
    const int*   adj    = (const int*)  d_in[1];
    const float* proj_w = (const float*)d_in[3];
    const float* proj_b = (const float*)d_in[4];
    const float* ln_s   = (const float*)d_in[5];
    const float* ln_b   = (const float*)d_in[6];
    const float* gat_W  = (const float*)d_in[7];
    const float* gat_a  = (const float*)d_in[8];
    const float* fw     = (const float*)d_in[9];
    const float* fb     = (const float*)d_in[10];
    const float* ow     = (const float*)d_in[11];
    const float* ob     = (const float*)d_in[12];
    float* out = (float*)d_out;

    float *hP, *xP, *whP;
    cudaGetSymbolAddress((void**)&hP,  g_h);
    cudaGetSymbolAddress((void**)&xP,  g_x);
    cudaGetSymbolAddress((void**)&whP, g_Wh);

    cudaFuncSetAttribute(attn_tc, cudaFuncAttributeMaxDynamicSharedMemorySize, SM_TOTAL);

    gemm16<<<T_N / 16, 256>>>(emb, proj_w, proj_b, hP, EMB, 1);
    rownorm0<<<1, 256>>>(0);
    cos_update<<<(NS + 7) / 8, 256>>>();

    for (int L = 0; L < 2; L++) {
        ln_k<<<T_N, 256>>>(ln_s + L * HID, ln_b + L * HID);
        gemm16<<<T_N / 16, 256>>>(xP, gat_W + (size_t)L * HID * HID, nullptr, whP, HID, 0);
        srcdst_k<<<T_N * NH / 8, 256>>>(gat_a + L * NH * 2 * HD);
        dmax_k<<<NH, 256>>>();
        attn_tc<<<128, 256, SM_TOTAL>>>(adj);
        combine_k<<<T_N * HID / 256, 256>>>();
    }

    rownorm0<<<1, 256>>>(1);
    scorecos_k<<<(NS + 7) / 8, 256>>>();
    softmax_k<<<1, 1024>>>();
    fusion_k<<<(NS + 15) / 16, 256>>>(fw, fb, ow, ob, out);
}